// round 1
// baseline (speedup 1.0000x reference)
#include <cuda_runtime.h>
#include <cstdint>

#define NB 8
#define NN 2048
#define DD 128
#define ALPHA 0.2f
#define NEG_INF_C (-9.0e15f)

// Scratch (device globals: no allocations allowed)
__device__ float g_Wh[(size_t)NB * NN * DD];   // 8 MB
__device__ float g_esrc[NB * NN];
__device__ float g_edst[NB * NN];
__device__ float g_m[NB * NN];
__device__ float g_zinv[NB * NN];

// ---------------------------------------------------------------------------
// Kernel A: Wh[b] = h[b] @ W.  grid (NN/64, NB), block 256, dyn smem 96KB.
// W_s[k][col] 64KB, hT[k][row] 32KB. Thread microtile 4 rows x 8 cols.
// ---------------------------------------------------------------------------
__global__ void __launch_bounds__(256) k_wh(const float* __restrict__ h,
                                            const float* __restrict__ W) {
    extern __shared__ float sm[];
    float* W_s = sm;             // [128][128]
    float* hT  = sm + 128 * 128; // [128][64]  (k-major for broadcast a-loads)

    const int b  = blockIdx.y;
    const int rb = blockIdx.x * 64;
    const int tid = threadIdx.x;
    const float* hb = h + ((size_t)b * NN + rb) * DD;

    for (int idx = tid * 4; idx < 128 * 128; idx += 1024)
        *(float4*)(W_s + idx) = *(const float4*)(W + idx);

    for (int idx = tid * 4; idx < 64 * 128; idx += 1024) {
        int row = idx >> 7, k = idx & 127;
        float4 v = *(const float4*)(hb + (size_t)row * DD + k);
        hT[(k + 0) * 64 + row] = v.x;
        hT[(k + 1) * 64 + row] = v.y;
        hT[(k + 2) * 64 + row] = v.z;
        hT[(k + 3) * 64 + row] = v.w;
    }
    __syncthreads();

    const int tx = tid & 15, ty = tid >> 4;
    float acc[4][8];
#pragma unroll
    for (int r = 0; r < 4; r++)
#pragma unroll
        for (int c = 0; c < 8; c++) acc[r][c] = 0.f;

#pragma unroll 8
    for (int k = 0; k < 128; ++k) {
        float4 av = *(const float4*)(hT + k * 64 + ty * 4);
        float a[4] = {av.x, av.y, av.z, av.w};
        float4 b0 = *(const float4*)(W_s + k * 128 + tx * 8);
        float4 b1 = *(const float4*)(W_s + k * 128 + tx * 8 + 4);
        float bb[8] = {b0.x, b0.y, b0.z, b0.w, b1.x, b1.y, b1.z, b1.w};
#pragma unroll
        for (int r = 0; r < 4; r++)
#pragma unroll
            for (int c = 0; c < 8; c++)
                acc[r][c] = fmaf(a[r], bb[c], acc[r][c]);
    }

#pragma unroll
    for (int r = 0; r < 4; r++) {
        size_t off = ((size_t)b * NN + rb + ty * 4 + r) * DD + tx * 8;
        *(float4*)(g_Wh + off)     = make_float4(acc[r][0], acc[r][1], acc[r][2], acc[r][3]);
        *(float4*)(g_Wh + off + 4) = make_float4(acc[r][4], acc[r][5], acc[r][6], acc[r][7]);
    }
}

// ---------------------------------------------------------------------------
// Kernel B: e_src/e_dst = Wh . a_src / a_dst. One warp per (b,n) row.
// grid NB*NN/8, block 256.
// ---------------------------------------------------------------------------
__global__ void __launch_bounds__(256) k_ed(const float* __restrict__ a_src,
                                            const float* __restrict__ a_dst) {
    int row  = blockIdx.x * 8 + (threadIdx.x >> 5);
    int lane = threadIdx.x & 31;
    float4 v  = *(const float4*)(g_Wh + (size_t)row * DD + lane * 4);
    float4 as = *(const float4*)(a_src + lane * 4);
    float4 ad = *(const float4*)(a_dst + lane * 4);
    float ps = v.x * as.x + v.y * as.y + v.z * as.z + v.w * as.w;
    float pd = v.x * ad.x + v.y * ad.y + v.z * ad.z + v.w * ad.w;
#pragma unroll
    for (int o = 16; o; o >>= 1) {
        ps += __shfl_down_sync(0xffffffffu, ps, o);
        pd += __shfl_down_sync(0xffffffffu, pd, o);
    }
    if (lane == 0) {
        g_esrc[row] = ps;
        g_edst[row] = pd;
    }
}

// ---------------------------------------------------------------------------
// Kernel C: per (b,i): m = masked max of f(s_i+d_j); zinv = 1/sum exp(.-m).
// LeakyReLU monotone -> m = f(s_i + max masked d_j). All-masked row: m=NEG_INF,
// Z=N (matches jax softmax over all-equal -9e15 logits). One CTA per i.
// ---------------------------------------------------------------------------
__global__ void __launch_bounds__(256) k_mz(const int* __restrict__ adj) {
    const int i = blockIdx.x;
    const int* arow = adj + (size_t)i * NN;
    __shared__ float sred[256];
    __shared__ int scnt[256];
    __shared__ float s_sv[NB], s_m[NB];
    __shared__ int s_total;
    const int tid = threadIdx.x;

    if (tid < NB) s_sv[tid] = g_esrc[tid * NN + i];

    int av[NN / 256];
#pragma unroll
    for (int t = 0; t < NN / 256; t++) av[t] = arow[tid + t * 256];

    float dmax[NB];
#pragma unroll
    for (int b = 0; b < NB; b++) dmax[b] = -3.4e38f;
    int cnt = 0;
#pragma unroll
    for (int t = 0; t < NN / 256; t++) {
        if (av[t] > 0) {
            int j = tid + t * 256;
            cnt++;
#pragma unroll
            for (int b = 0; b < NB; b++)
                dmax[b] = fmaxf(dmax[b], g_edst[b * NN + j]);
        }
    }
    scnt[tid] = cnt;
    __syncthreads();
    for (int s = 128; s > 0; s >>= 1) {
        if (tid < s) scnt[tid] += scnt[tid + s];
        __syncthreads();
    }
    if (tid == 0) s_total = scnt[0];
    __syncthreads();
    const int total = s_total;

#pragma unroll
    for (int b = 0; b < NB; b++) {
        sred[tid] = dmax[b];
        __syncthreads();
        for (int s = 128; s > 0; s >>= 1) {
            if (tid < s) sred[tid] = fmaxf(sred[tid], sred[tid + s]);
            __syncthreads();
        }
        if (tid == 0) {
            float m;
            if (total > 0) {
                float e = s_sv[b] + sred[0];
                m = e > 0.f ? e : ALPHA * e;
            } else {
                m = NEG_INF_C;
            }
            s_m[b] = m;
            g_m[b * NN + i] = m;
        }
        __syncthreads();
    }

    float z[NB];
#pragma unroll
    for (int b = 0; b < NB; b++) z[b] = 0.f;
#pragma unroll
    for (int t = 0; t < NN / 256; t++) {
        if (av[t] > 0) {
            int j = tid + t * 256;
#pragma unroll
            for (int b = 0; b < NB; b++) {
                float e = s_sv[b] + g_edst[b * NN + j];
                e = e > 0.f ? e : ALPHA * e;
                z[b] += __expf(e - s_m[b]);
            }
        }
    }
#pragma unroll
    for (int b = 0; b < NB; b++) {
        sred[tid] = z[b];
        __syncthreads();
        for (int s = 128; s > 0; s >>= 1) {
            if (tid < s) sred[tid] += sred[tid + s];
            __syncthreads();
        }
        if (tid == 0) {
            float Z = total > 0 ? sred[0] : (float)NN;
            g_zinv[b * NN + i] = 1.f / Z;
        }
        __syncthreads();
    }
}

// ---------------------------------------------------------------------------
// Kernel D (dominant): h'[b, i0:i0+128, :] = P @ Wh[b], P generated on the fly.
// grid (NN/128, NB) = 128 CTAs, block 256, 8x8 register microtiles.
// w_s padded to 33 floats/row: conflict-free STS and broadcast a-LDS.
// ---------------------------------------------------------------------------
__global__ void __launch_bounds__(256) k_main(const int* __restrict__ adj,
                                              float* __restrict__ out) {
    __shared__ float w_s[128 * 33];                 // [i][k] padded
    __shared__ __align__(16) float wh_s[32 * 128];  // [k][col]
    __shared__ float sv_s[128], m_s[128], zi_s[128];

    const int b  = blockIdx.y;
    const int i0 = blockIdx.x * 128;
    const int tid = threadIdx.x;

    if (tid < 128) {
        sv_s[tid] = g_esrc[b * NN + i0 + tid];
        m_s[tid]  = g_m[b * NN + i0 + tid];
        zi_s[tid] = g_zinv[b * NN + i0 + tid];
    }

    const int tx = tid & 15, ty = tid >> 4;
    float acc[8][8];
#pragma unroll
    for (int r = 0; r < 8; r++)
#pragma unroll
        for (int c = 0; c < 8; c++) acc[r][c] = 0.f;

    __syncthreads();

    for (int jc = 0; jc < NN; jc += 32) {
        // P tile: 128 rows x 32 cols; warp reads 32 consecutive adj ints.
#pragma unroll
        for (int it = 0; it < 16; ++it) {
            int idx = tid + it * 256;
            int il = idx >> 5, jl = idx & 31;
            int a = adj[(size_t)(i0 + il) * NN + jc + jl];
            float mi = m_s[il];
            float w;
            if (a > 0) {
                float e = sv_s[il] + g_edst[b * NN + jc + jl];
                e = e > 0.f ? e : ALPHA * e;
                w = __expf(e - mi) * zi_s[il];
            } else {
                w = (mi <= -8.9e15f) ? zi_s[il] : 0.f;  // all-masked-row fallback
            }
            w_s[il * 33 + jl] = w;
        }
        // Wh tile: 32 rows x 128 cols, float4 coalesced.
#pragma unroll
        for (int it = 0; it < 4; ++it) {
            int idx = tid * 4 + it * 1024;
            int jl = idx >> 7, col = idx & 127;
            *(float4*)(wh_s + idx) =
                *(const float4*)(g_Wh + ((size_t)b * NN + jc + jl) * DD + col);
        }
        __syncthreads();

#pragma unroll 8
        for (int k = 0; k < 32; ++k) {
            float4 b0 = *(const float4*)(wh_s + k * 128 + tx * 8);
            float4 b1 = *(const float4*)(wh_s + k * 128 + tx * 8 + 4);
            float bb[8] = {b0.x, b0.y, b0.z, b0.w, b1.x, b1.y, b1.z, b1.w};
            float aa[8];
#pragma unroll
            for (int r = 0; r < 8; r++) aa[r] = w_s[(ty * 8 + r) * 33 + k];
#pragma unroll
            for (int r = 0; r < 8; r++)
#pragma unroll
                for (int c = 0; c < 8; c++)
                    acc[r][c] = fmaf(aa[r], bb[c], acc[r][c]);
        }
        __syncthreads();
    }

#pragma unroll
    for (int r = 0; r < 8; r++) {
        size_t off = ((size_t)b * NN + i0 + ty * 8 + r) * DD + tx * 8;
        *(float4*)(out + off)     = make_float4(acc[r][0], acc[r][1], acc[r][2], acc[r][3]);
        *(float4*)(out + off + 4) = make_float4(acc[r][4], acc[r][5], acc[r][6], acc[r][7]);
    }
}

// ---------------------------------------------------------------------------
extern "C" void kernel_launch(void* const* d_in, const int* in_sizes, int n_in,
                              void* d_out, int out_size) {
    const float* h     = (const float*)d_in[0];
    const int*   adj   = (const int*)d_in[1];
    const float* W     = (const float*)d_in[2];
    const float* a_src = (const float*)d_in[3];
    const float* a_dst = (const float*)d_in[4];
    float* out = (float*)d_out;

    cudaFuncSetAttribute(k_wh, cudaFuncAttributeMaxDynamicSharedMemorySize, 98304);

    k_wh<<<dim3(NN / 64, NB), 256, 98304>>>(h, W);
    k_ed<<<NB * NN / 8, 256>>>(a_src, a_dst);
    k_mz<<<NN, 256>>>(adj);
    k_main<<<dim3(NN / 128, NB), 256>>>(adj, out);
}

// round 3
// speedup vs baseline: 2.0390x; 2.0390x over previous
#include <cuda_runtime.h>
#include <cstdint>

#define NB 8
#define NN 2048
#define DD 128
#define ALPHA 0.2f

// ---------------------------------------------------------------------------
// helpers
// ---------------------------------------------------------------------------
__device__ __forceinline__ float to_tf32(float x) {
    uint32_t u;
    asm("cvt.rna.tf32.f32 %0, %1;" : "=r"(u) : "f"(x));
    return __uint_as_float(u);
}

__device__ __forceinline__ void mma_tf32(float* d, const uint32_t* a,
                                         const uint32_t* b) {
    asm volatile(
        "mma.sync.aligned.m16n8k8.row.col.f32.tf32.tf32.f32 "
        "{%0,%1,%2,%3}, {%4,%5,%6,%7}, {%8,%9}, {%0,%1,%2,%3};"
        : "+f"(d[0]), "+f"(d[1]), "+f"(d[2]), "+f"(d[3])
        : "r"(a[0]), "r"(a[1]), "r"(a[2]), "r"(a[3]), "r"(b[0]), "r"(b[1]));
}

// ---------------------------------------------------------------------------
// Scratch
// ---------------------------------------------------------------------------
__device__ float g_Wh[(size_t)NB * NN * DD];  // [b][n][d], tf32-rounded, 8 MB
__device__ float g_esrc[NB * NN];
__device__ float g_edst[NB * NN];

// ---------------------------------------------------------------------------
// Kernel A: Wh = h @ W (tf32-rounded store) + fused e_src/e_dst.
// grid (32, 8), block 256, 96KB dynamic smem.
// ---------------------------------------------------------------------------
__global__ void __launch_bounds__(256) k_wh(const float* __restrict__ h,
                                            const float* __restrict__ W,
                                            const float* __restrict__ a_src,
                                            const float* __restrict__ a_dst) {
    extern __shared__ float sm[];
    float* W_s = sm;             // [128][128] 64KB
    float* hT  = sm + 128 * 128; // [128][64]  32KB

    const int b  = blockIdx.y;
    const int rb = blockIdx.x * 64;
    const int tid = threadIdx.x;
    const float* hb = h + ((size_t)b * NN + rb) * DD;

    for (int idx = tid * 4; idx < 128 * 128; idx += 1024)
        *(float4*)(W_s + idx) = *(const float4*)(W + idx);

    for (int idx = tid * 4; idx < 64 * 128; idx += 1024) {
        int row = idx >> 7, k = idx & 127;
        float4 v = *(const float4*)(hb + (size_t)row * DD + k);
        hT[(k + 0) * 64 + row] = v.x;
        hT[(k + 1) * 64 + row] = v.y;
        hT[(k + 2) * 64 + row] = v.z;
        hT[(k + 3) * 64 + row] = v.w;
    }
    __syncthreads();

    const int tx = tid & 15, ty = tid >> 4;
    float acc[4][8];
#pragma unroll
    for (int r = 0; r < 4; r++)
#pragma unroll
        for (int c = 0; c < 8; c++) acc[r][c] = 0.f;

#pragma unroll 8
    for (int k = 0; k < 128; ++k) {
        float4 av = *(const float4*)(hT + k * 64 + ty * 4);
        float a[4] = {av.x, av.y, av.z, av.w};
        float4 b0 = *(const float4*)(W_s + k * 128 + tx * 8);
        float4 b1 = *(const float4*)(W_s + k * 128 + tx * 8 + 4);
        float bb[8] = {b0.x, b0.y, b0.z, b0.w, b1.x, b1.y, b1.z, b1.w};
#pragma unroll
        for (int r = 0; r < 4; r++)
#pragma unroll
            for (int c = 0; c < 8; c++)
                acc[r][c] = fmaf(a[r], bb[c], acc[r][c]);
    }

    // fused e_src / e_dst
    {
        float4 s0 = *(const float4*)(a_src + tx * 8);
        float4 s1 = *(const float4*)(a_src + tx * 8 + 4);
        float4 d0 = *(const float4*)(a_dst + tx * 8);
        float4 d1 = *(const float4*)(a_dst + tx * 8 + 4);
        float as[8] = {s0.x, s0.y, s0.z, s0.w, s1.x, s1.y, s1.z, s1.w};
        float ad[8] = {d0.x, d0.y, d0.z, d0.w, d1.x, d1.y, d1.z, d1.w};
#pragma unroll
        for (int r = 0; r < 4; r++) {
            float ps = 0.f, pd = 0.f;
#pragma unroll
            for (int c = 0; c < 8; c++) {
                ps = fmaf(acc[r][c], as[c], ps);
                pd = fmaf(acc[r][c], ad[c], pd);
            }
#pragma unroll
            for (int o = 8; o; o >>= 1) {
                ps += __shfl_xor_sync(0xffffffffu, ps, o);
                pd += __shfl_xor_sync(0xffffffffu, pd, o);
            }
            if (tx == 0) {
                g_esrc[b * NN + rb + ty * 4 + r] = ps;
                g_edst[b * NN + rb + ty * 4 + r] = pd;
            }
        }
    }

    // store, tf32-rounded (B operand of k_tc)
#pragma unroll
    for (int r = 0; r < 4; r++) {
        size_t off = ((size_t)b * NN + rb + ty * 4 + r) * DD + tx * 8;
        *(float4*)(g_Wh + off) =
            make_float4(to_tf32(acc[r][0]), to_tf32(acc[r][1]),
                        to_tf32(acc[r][2]), to_tf32(acc[r][3]));
        *(float4*)(g_Wh + off + 4) =
            make_float4(to_tf32(acc[r][4]), to_tf32(acc[r][5]),
                        to_tf32(acc[r][6]), to_tf32(acc[r][7]));
    }
}

// ---------------------------------------------------------------------------
// Kernel B: fused flash-GAT via mma.sync tf32 (m16n8k8).
// CTA = (b, 128-row i-tile); 8 warps 2(M)x4(N); warp tile 64x32.
// A = on-the-fly unnormalized attention weights; Z row sums in regs;
// epilogue scales by 1/Z. Masked entries get 1e-30 so all-masked rows
// reduce to the exact uniform softmax.
// ---------------------------------------------------------------------------
__global__ void __launch_bounds__(256) k_tc(const int* __restrict__ adj,
                                            float* __restrict__ out) {
    __shared__ float A_perm[128 * 36];  // [i][k&3][k>>2], pad 36
    __shared__ float B_s[32 * 136];     // [k][n], pad 136
    __shared__ float sv_s[128];
    __shared__ float z_s[128];

    const int tid = threadIdx.x, lane = tid & 31, wid = tid >> 5;
    const int wm = wid >> 2, wn = wid & 3;  // 2 x 4 warp grid
    const int b  = blockIdx.y;
    const int i0 = blockIdx.x * 128;

    if (tid < 128) sv_s[tid] = g_esrc[b * NN + i0 + tid];

    const float* edst = g_edst + b * NN;
    const float* whB  = g_Wh + (size_t)b * NN * DD;

    float acc[4][4][4];
#pragma unroll
    for (int mf = 0; mf < 4; mf++)
#pragma unroll
        for (int nf = 0; nf < 4; nf++)
#pragma unroll
            for (int q = 0; q < 4; q++) acc[mf][nf][q] = 0.f;

    float zacc[16];
#pragma unroll
    for (int it = 0; it < 16; it++) zacc[it] = 0.f;

    const int c = lane & 3;   // k phase within fragment
    const int rq = lane >> 2; // row/col quad index

    __syncthreads();

    for (int t = 0; t < 64; ++t) {
        const int jc = t * 32;

        // --- A tile: w[128 i][32 j] into permuted layout ---
        const float ed = edst[jc + lane];  // jl == lane for all 16 iters
#pragma unroll
        for (int it = 0; it < 16; ++it) {
            int il = wid + it * 8;
            int a = adj[(size_t)(i0 + il) * NN + jc + lane];
            float e = sv_s[il] + ed;
            e = e > 0.f ? e : ALPHA * e;
            float w = (a > 0) ? __expf(e) : 1e-30f;
            w = to_tf32(w);
            zacc[it] += w;
            A_perm[il * 36 + (lane & 3) * 8 + (lane >> 2)] = w;
        }

        // --- B tile: Wh[32 j][128 d], coalesced float4, pad 136 ---
#pragma unroll
        for (int it = 0; it < 4; ++it) {
            int idx = tid + it * 256;
            int jl = idx >> 5, d4 = idx & 31;
            float4 v = *(const float4*)(whB + (size_t)(jc + jl) * DD + d4 * 4);
            *(float4*)(B_s + jl * 136 + d4 * 4) = v;
        }
        __syncthreads();

        // --- fragments + mma ---
        uint32_t breg[4][4][2];
        {
            const int nbase = wn * 32 + rq;
#pragma unroll
            for (int nf = 0; nf < 4; ++nf)
#pragma unroll
                for (int kk = 0; kk < 4; ++kk) {
                    breg[nf][kk][0] =
                        __float_as_uint(B_s[(kk * 8 + c) * 136 + nbase + nf * 8]);
                    breg[nf][kk][1] =
                        __float_as_uint(B_s[(kk * 8 + 4 + c) * 136 + nbase + nf * 8]);
                }
        }

#pragma unroll
        for (int mf = 0; mf < 4; ++mf) {
            const int r0 = wm * 64 + mf * 16 + rq;
            float4 lo0 = *(const float4*)(A_perm + r0 * 36 + c * 8);
            float4 lo1 = *(const float4*)(A_perm + r0 * 36 + c * 8 + 4);
            float4 hi0 = *(const float4*)(A_perm + (r0 + 8) * 36 + c * 8);
            float4 hi1 = *(const float4*)(A_perm + (r0 + 8) * 36 + c * 8 + 4);
            float aLo[8] = {lo0.x, lo0.y, lo0.z, lo0.w, lo1.x, lo1.y, lo1.z, lo1.w};
            float aHi[8] = {hi0.x, hi0.y, hi0.z, hi0.w, hi1.x, hi1.y, hi1.z, hi1.w};
#pragma unroll
            for (int kk = 0; kk < 4; ++kk) {
                uint32_t areg[4] = {
                    __float_as_uint(aLo[2 * kk]), __float_as_uint(aHi[2 * kk]),
                    __float_as_uint(aLo[2 * kk + 1]), __float_as_uint(aHi[2 * kk + 1])};
#pragma unroll
                for (int nf = 0; nf < 4; ++nf)
                    mma_tf32(acc[mf][nf], areg, breg[nf][kk]);
            }
        }
        __syncthreads();
    }

    // row sums -> z_s (each (wid, it) owns a unique row)
#pragma unroll
    for (int it = 0; it < 16; ++it) {
        float v = zacc[it];
#pragma unroll
        for (int o = 16; o; o >>= 1) v += __shfl_down_sync(0xffffffffu, v, o);
        if (lane == 0) z_s[wid + it * 8] = v;
    }
    __syncthreads();

    // epilogue: normalize + store (float2 per fragment half)
#pragma unroll
    for (int mf = 0; mf < 4; ++mf) {
        const int r0 = wm * 64 + mf * 16 + rq;
        const float zi0 = 1.f / z_s[r0];
        const float zi1 = 1.f / z_s[r0 + 8];
#pragma unroll
        for (int nf = 0; nf < 4; ++nf) {
            const int cc = wn * 32 + nf * 8 + 2 * c;
            size_t o0 = ((size_t)b * NN + i0 + r0) * DD + cc;
            size_t o1 = ((size_t)b * NN + i0 + r0 + 8) * DD + cc;
            *(float2*)(out + o0) =
                make_float2(acc[mf][nf][0] * zi0, acc[mf][nf][1] * zi0);
            *(float2*)(out + o1) =
                make_float2(acc[mf][nf][2] * zi1, acc[mf][nf][3] * zi1);
        }
    }
}

// ---------------------------------------------------------------------------
extern "C" void kernel_launch(void* const* d_in, const int* in_sizes, int n_in,
                              void* d_out, int out_size) {
    const float* h     = (const float*)d_in[0];
    const int*   adj   = (const int*)d_in[1];
    const float* W     = (const float*)d_in[2];
    const float* a_src = (const float*)d_in[3];
    const float* a_dst = (const float*)d_in[4];
    float* out = (float*)d_out;

    cudaFuncSetAttribute(k_wh, cudaFuncAttributeMaxDynamicSharedMemorySize, 98304);

    k_wh<<<dim3(NN / 64, NB), 256, 98304>>>(h, W, a_src, a_dst);
    k_tc<<<dim3(NN / 128, NB), 256>>>(adj, out);
}

// round 4
// speedup vs baseline: 3.7683x; 1.8481x over previous
#include <cuda_runtime.h>
#include <cstdint>

#define NB 8
#define NN 2048
#define DD 128
#define ALPHA 0.2f

// ---------------------------------------------------------------------------
// helpers
// ---------------------------------------------------------------------------
__device__ __forceinline__ float to_tf32(float x) {
    uint32_t u;
    asm("cvt.rna.tf32.f32 %0, %1;" : "=r"(u) : "f"(x));
    return __uint_as_float(u);
}

__device__ __forceinline__ void mma_tf32(float* d, const uint32_t* a,
                                         const uint32_t* b) {
    asm volatile(
        "mma.sync.aligned.m16n8k8.row.col.f32.tf32.tf32.f32 "
        "{%0,%1,%2,%3}, {%4,%5,%6,%7}, {%8,%9}, {%0,%1,%2,%3};"
        : "+f"(d[0]), "+f"(d[1]), "+f"(d[2]), "+f"(d[3])
        : "r"(a[0]), "r"(a[1]), "r"(a[2]), "r"(a[3]), "r"(b[0]), "r"(b[1]));
}

__device__ __forceinline__ uint32_t smem_u32(const void* p) {
    uint32_t a;
    asm("{ .reg .u64 t; cvta.to.shared.u64 t, %1; cvt.u32.u64 %0, t; }"
        : "=r"(a) : "l"(p));
    return a;
}

#define CP_ASYNC16(dst, src) \
    asm volatile("cp.async.cg.shared.global [%0], [%1], 16;" \
                 :: "r"(dst), "l"(src) : "memory")
#define CP_COMMIT asm volatile("cp.async.commit_group;" ::: "memory")
#define CP_WAIT0  asm volatile("cp.async.wait_group 0;" ::: "memory")

// ---------------------------------------------------------------------------
// Scratch
// ---------------------------------------------------------------------------
__device__ float g_Wh[(size_t)NB * NN * DD];  // [b][n][d], tf32-rounded, 8 MB
__device__ float g_esrc[NB * NN];
__device__ float g_edst[NB * NN];

// ---------------------------------------------------------------------------
// Kernel A: Wh = h @ W (tf32-rounded store) + fused e_src/e_dst.
// grid (32, 8), block 256, 96KB dynamic smem. (proven in rounds 1-3)
// ---------------------------------------------------------------------------
__global__ void __launch_bounds__(256) k_wh(const float* __restrict__ h,
                                            const float* __restrict__ W,
                                            const float* __restrict__ a_src,
                                            const float* __restrict__ a_dst) {
    extern __shared__ float sm[];
    float* W_s = sm;             // [128][128] 64KB
    float* hT  = sm + 128 * 128; // [128][64]  32KB

    const int b  = blockIdx.y;
    const int rb = blockIdx.x * 64;
    const int tid = threadIdx.x;
    const float* hb = h + ((size_t)b * NN + rb) * DD;

    for (int idx = tid * 4; idx < 128 * 128; idx += 1024)
        *(float4*)(W_s + idx) = *(const float4*)(W + idx);

    for (int idx = tid * 4; idx < 64 * 128; idx += 1024) {
        int row = idx >> 7, k = idx & 127;
        float4 v = *(const float4*)(hb + (size_t)row * DD + k);
        hT[(k + 0) * 64 + row] = v.x;
        hT[(k + 1) * 64 + row] = v.y;
        hT[(k + 2) * 64 + row] = v.z;
        hT[(k + 3) * 64 + row] = v.w;
    }
    __syncthreads();

    const int tx = tid & 15, ty = tid >> 4;
    float acc[4][8];
#pragma unroll
    for (int r = 0; r < 4; r++)
#pragma unroll
        for (int c = 0; c < 8; c++) acc[r][c] = 0.f;

#pragma unroll 8
    for (int k = 0; k < 128; ++k) {
        float4 av = *(const float4*)(hT + k * 64 + ty * 4);
        float a[4] = {av.x, av.y, av.z, av.w};
        float4 b0 = *(const float4*)(W_s + k * 128 + tx * 8);
        float4 b1 = *(const float4*)(W_s + k * 128 + tx * 8 + 4);
        float bb[8] = {b0.x, b0.y, b0.z, b0.w, b1.x, b1.y, b1.z, b1.w};
#pragma unroll
        for (int r = 0; r < 4; r++)
#pragma unroll
            for (int c = 0; c < 8; c++)
                acc[r][c] = fmaf(a[r], bb[c], acc[r][c]);
    }

    // fused e_src / e_dst
    {
        float4 s0 = *(const float4*)(a_src + tx * 8);
        float4 s1 = *(const float4*)(a_src + tx * 8 + 4);
        float4 d0 = *(const float4*)(a_dst + tx * 8);
        float4 d1 = *(const float4*)(a_dst + tx * 8 + 4);
        float as[8] = {s0.x, s0.y, s0.z, s0.w, s1.x, s1.y, s1.z, s1.w};
        float ad[8] = {d0.x, d0.y, d0.z, d0.w, d1.x, d1.y, d1.z, d1.w};
#pragma unroll
        for (int r = 0; r < 4; r++) {
            float ps = 0.f, pd = 0.f;
#pragma unroll
            for (int c = 0; c < 8; c++) {
                ps = fmaf(acc[r][c], as[c], ps);
                pd = fmaf(acc[r][c], ad[c], pd);
            }
#pragma unroll
            for (int o = 8; o; o >>= 1) {
                ps += __shfl_xor_sync(0xffffffffu, ps, o);
                pd += __shfl_xor_sync(0xffffffffu, pd, o);
            }
            if (tx == 0) {
                g_esrc[b * NN + rb + ty * 4 + r] = ps;
                g_edst[b * NN + rb + ty * 4 + r] = pd;
            }
        }
    }

    // store, tf32-rounded (B operand of k_tc)
#pragma unroll
    for (int r = 0; r < 4; r++) {
        size_t off = ((size_t)b * NN + rb + ty * 4 + r) * DD + tx * 8;
        *(float4*)(g_Wh + off) =
            make_float4(to_tf32(acc[r][0]), to_tf32(acc[r][1]),
                        to_tf32(acc[r][2]), to_tf32(acc[r][3]));
        *(float4*)(g_Wh + off + 4) =
            make_float4(to_tf32(acc[r][4]), to_tf32(acc[r][5]),
                        to_tf32(acc[r][6]), to_tf32(acc[r][7]));
    }
}

// ---------------------------------------------------------------------------
// Kernel B: fused flash-GAT, tf32 mma.sync, 512 threads, double-buffered,
// cp.async B-tiles, adj prefetch, single sync per K-chunk.
// CTA = (b, 128-row i-tile); warps 4(M)x4(N); warp tile 32x32.
// SMEM floats: A_perm 2x[128][36] | B_s 2x[32][136] | ed[2048] | sv[128] | z[128]
// ---------------------------------------------------------------------------
#define APERM_F 4608   // 128*36
#define BS_F    4352   // 32*136
#define OFF_B   (2 * APERM_F)
#define OFF_ED  (OFF_B + 2 * BS_F)
#define OFF_SV  (OFF_ED + 2048)
#define OFF_Z   (OFF_SV + 128)
#define SMEM_TC ((OFF_Z + 128) * 4)   // 80896 bytes

__global__ void __launch_bounds__(512, 1) k_tc(const int* __restrict__ adj,
                                               float* __restrict__ out) {
    extern __shared__ float sm[];
    float* A_perm = sm;
    float* B_s    = sm + OFF_B;
    float* ed_s   = sm + OFF_ED;
    float* sv_s   = sm + OFF_SV;
    float* z_s    = sm + OFF_Z;

    const int tid = threadIdx.x, lane = tid & 31, wid = tid >> 5;
    const int wm = wid >> 2, wn = wid & 3;  // 4 x 4 warp grid
    const int b  = blockIdx.y;
    const int i0 = blockIdx.x * 128;
    const int c = lane & 3, rq = lane >> 2;

    // preload edst row + esrc slice
    *(float4*)(ed_s + tid * 4) = *(const float4*)(g_edst + b * NN + tid * 4);
    if (tid < 128) sv_s[tid] = g_esrc[b * NN + i0 + tid];

    const float* whB = g_Wh + (size_t)b * NN * DD;
    const int* adj_t = adj + (size_t)(i0 + wid) * NN + lane;
    const uint32_t B_u32 = smem_u32(B_s);

    float acc[2][4][4];
#pragma unroll
    for (int mf = 0; mf < 2; mf++)
#pragma unroll
        for (int nf = 0; nf < 4; nf++)
#pragma unroll
            for (int q = 0; q < 4; q++) acc[mf][nf][q] = 0.f;
    float zacc[8];
#pragma unroll
    for (int it = 0; it < 8; it++) zacc[it] = 0.f;
    int adjreg[8];

    __syncthreads();  // ed_s / sv_s ready

    // ---- prologue: tile 0 ----
#pragma unroll
    for (int it = 0; it < 8; it++) adjreg[it] = adj_t[it * 16 * NN];
#pragma unroll
    for (int it = 0; it < 2; it++) {
        int idx = tid + it * 512;
        int jl = idx >> 5, d4 = idx & 31;
        CP_ASYNC16(B_u32 + (uint32_t)(jl * 136 + d4 * 4) * 4,
                   whB + (size_t)jl * DD + d4 * 4);
    }
    CP_COMMIT;
#pragma unroll
    for (int it = 0; it < 8; it++) {
        int il = wid + it * 16;
        float e = sv_s[il] + ed_s[lane];
        e = e > 0.f ? e : ALPHA * e;
        float w = (adjreg[it] > 0) ? __expf(e) : 1e-30f;
        w = to_tf32(w);
        zacc[it] += w;
        A_perm[il * 36 + c * 8 + rq] = w;
    }
    CP_WAIT0;
    __syncthreads();

    // ---- main loop: 64 K-chunks of 32 ----
    for (int t = 0; t < 64; ++t) {
        const int cur = t & 1;
        const float* Ac = A_perm + cur * APERM_F;
        const float* Bc = B_s + cur * BS_F;
        const int jcn = (t + 1) * 32;

        if (t < 63) {
            // prefetch adj for t+1 (latency hidden under MMA below)
#pragma unroll
            for (int it = 0; it < 8; it++)
                adjreg[it] = adj_t[it * 16 * NN + jcn];
            // cp.async B tile t+1
            const uint32_t Bn = B_u32 + (uint32_t)((cur ^ 1) * BS_F) * 4;
#pragma unroll
            for (int it = 0; it < 2; it++) {
                int idx = tid + it * 512;
                int jl = idx >> 5, d4 = idx & 31;
                CP_ASYNC16(Bn + (uint32_t)(jl * 136 + d4 * 4) * 4,
                           whB + (size_t)(jcn + jl) * DD + d4 * 4);
            }
            CP_COMMIT;
        }

        // ---- B fragments (reused across mf) ----
        uint32_t breg[4][4][2];
        const int nbase = wn * 32 + rq;
#pragma unroll
        for (int nf = 0; nf < 4; ++nf)
#pragma unroll
            for (int kk = 0; kk < 4; ++kk) {
                breg[nf][kk][0] =
                    __float_as_uint(Bc[(kk * 8 + c) * 136 + nbase + nf * 8]);
                breg[nf][kk][1] =
                    __float_as_uint(Bc[(kk * 8 + 4 + c) * 136 + nbase + nf * 8]);
            }

        // ---- A fragments + MMA ----
#pragma unroll
        for (int mf = 0; mf < 2; ++mf) {
            const int r0 = wm * 32 + mf * 16 + rq;
            float4 lo0 = *(const float4*)(Ac + r0 * 36 + c * 8);
            float4 lo1 = *(const float4*)(Ac + r0 * 36 + c * 8 + 4);
            float4 hi0 = *(const float4*)(Ac + (r0 + 8) * 36 + c * 8);
            float4 hi1 = *(const float4*)(Ac + (r0 + 8) * 36 + c * 8 + 4);
            float aLo[8] = {lo0.x, lo0.y, lo0.z, lo0.w, lo1.x, lo1.y, lo1.z, lo1.w};
            float aHi[8] = {hi0.x, hi0.y, hi0.z, hi0.w, hi1.x, hi1.y, hi1.z, hi1.w};
#pragma unroll
            for (int kk = 0; kk < 4; ++kk) {
                uint32_t areg[4] = {
                    __float_as_uint(aLo[2 * kk]), __float_as_uint(aHi[2 * kk]),
                    __float_as_uint(aLo[2 * kk + 1]), __float_as_uint(aHi[2 * kk + 1])};
#pragma unroll
                for (int nf = 0; nf < 4; ++nf)
                    mma_tf32(acc[mf][nf], areg, breg[nf][kk]);
            }
        }

        if (t < 63) {
            // generate A tile t+1 into the other buffer
            float* An = A_perm + (cur ^ 1) * APERM_F;
#pragma unroll
            for (int it = 0; it < 8; it++) {
                int il = wid + it * 16;
                float e = sv_s[il] + ed_s[jcn + lane];
                e = e > 0.f ? e : ALPHA * e;
                float w = (adjreg[it] > 0) ? __expf(e) : 1e-30f;
                w = to_tf32(w);
                zacc[it] += w;
                An[il * 36 + c * 8 + rq] = w;
            }
            CP_WAIT0;
        }
        __syncthreads();
    }

    // ---- Z row sums ----
#pragma unroll
    for (int it = 0; it < 8; ++it) {
        float v = zacc[it];
#pragma unroll
        for (int o = 16; o; o >>= 1) v += __shfl_down_sync(0xffffffffu, v, o);
        if (lane == 0) z_s[wid + it * 16] = v;
    }
    __syncthreads();

    // ---- epilogue: normalize + store ----
#pragma unroll
    for (int mf = 0; mf < 2; ++mf) {
        const int r0 = wm * 32 + mf * 16 + rq;
        const float zi0 = 1.f / z_s[r0];
        const float zi1 = 1.f / z_s[r0 + 8];
#pragma unroll
        for (int nf = 0; nf < 4; ++nf) {
            const int cc = wn * 32 + nf * 8 + 2 * c;
            size_t o0 = ((size_t)b * NN + i0 + r0) * DD + cc;
            size_t o1 = ((size_t)b * NN + i0 + r0 + 8) * DD + cc;
            *(float2*)(out + o0) =
                make_float2(acc[mf][nf][0] * zi0, acc[mf][nf][1] * zi0);
            *(float2*)(out + o1) =
                make_float2(acc[mf][nf][2] * zi1, acc[mf][nf][3] * zi1);
        }
    }
}

// ---------------------------------------------------------------------------
extern "C" void kernel_launch(void* const* d_in, const int* in_sizes, int n_in,
                              void* d_out, int out_size) {
    const float* h     = (const float*)d_in[0];
    const int*   adj   = (const int*)d_in[1];
    const float* W     = (const float*)d_in[2];
    const float* a_src = (const float*)d_in[3];
    const float* a_dst = (const float*)d_in[4];
    float* out = (float*)d_out;

    cudaFuncSetAttribute(k_wh, cudaFuncAttributeMaxDynamicSharedMemorySize, 98304);
    cudaFuncSetAttribute(k_tc, cudaFuncAttributeMaxDynamicSharedMemorySize, SMEM_TC);

    k_wh<<<dim3(NN / 64, NB), 256, 98304>>>(h, W, a_src, a_dst);
    k_tc<<<dim3(NN / 128, NB), 512, SMEM_TC>>>(adj, out);
}